// round 1
// baseline (speedup 1.0000x reference)
#include <cuda_runtime.h>

// Problem constants
#define NB   1024        // batch (RoIs)
#define NC   256         // channels
#define HW   49          // 7*7 spatial
#define FEAT 12544       // 256*49
#define REP  1024
#define GRAM 2401        // 49*49

// Scratch (no allocations allowed -> device globals)
__device__ float g_G  [NB  * GRAM];   // 9.8 MB  Gram matrices
__device__ float g_W1g[REP * GRAM];   // 9.8 MB  folded FC1 weight
__device__ float g_Y1 [NB  * REP];    // 4 MB
__device__ float g_Y2 [NB  * REP];    // 4 MB

// ---------------------------------------------------------------------------
// Kernel 1: fold W1[1024, 12544] into W1g[1024, 2401].
// corr feature f = (ph*16+pw)*49 + ij maps to Gram entry (ij, ij2) with
// ij2 = ij + (2ph-14, 2pw-14).  Inverse: (ij, ij2) valid iff both spatial
// displacements are even; then ph=(di+14)/2, pw=(dj+14)/2.  Odd-displacement
// pairs contribute 0 (corr is exactly 0 there due to zero padding).
// ---------------------------------------------------------------------------
__global__ void build_w1g_kernel(const float* __restrict__ W1, float* __restrict__ W1g) {
    int idx = blockIdx.x * blockDim.x + threadIdx.x;
    if (idx >= REP * GRAM) return;
    int r   = idx / GRAM;
    int rem = idx - r * GRAM;
    int ij  = rem / 49;
    int ij2 = rem - ij * 49;
    int i  = ij  / 7, j  = ij  - i  * 7;
    int i2 = ij2 / 7, j2 = ij2 - i2 * 7;
    int di = i2 - i + 14;   // in [8,20]
    int dj = j2 - j + 14;
    float v = 0.0f;
    if (((di | dj) & 1) == 0) {
        int ph = di >> 1;   // in [4,10] subset of [0,15]
        int pw = dj >> 1;
        int f  = (ph * 16 + pw) * 49 + ij;
        v = W1[r * FEAT + f];
    }
    W1g[idx] = v;
}

// ---------------------------------------------------------------------------
// Kernel 2: batched Gram  G[b] = x1[b]^T @ x2[b],  [49x49], K = 256.
// One CTA per b. 16x16 threads, 4x4 micro-tile over a padded 64x64 tile.
// x layout is [C][HW] so smem tiles load coalesced directly as [k][m].
// ---------------------------------------------------------------------------
__global__ void gram_kernel(const float* __restrict__ x1,
                            const float* __restrict__ x2,
                            float* __restrict__ G) {
    __shared__ __align__(16) float As[32][64];
    __shared__ __align__(16) float Bs[32][64];
    int b = blockIdx.x;
    int t = threadIdx.x;
    int tx = t & 15, ty = t >> 4;
    const float* X1 = x1 + (size_t)b * NC * HW;
    const float* X2 = x2 + (size_t)b * NC * HW;

    float acc[4][4] = {};

    for (int k0 = 0; k0 < NC; k0 += 32) {
        #pragma unroll
        for (int q = t; q < 32 * 64; q += 256) {
            int k = q >> 6, m = q & 63;
            float a = 0.0f, bb = 0.0f;
            if (m < HW) {
                a  = X1[(k0 + k) * HW + m];
                bb = X2[(k0 + k) * HW + m];
            }
            As[k][m] = a;
            Bs[k][m] = bb;
        }
        __syncthreads();
        #pragma unroll
        for (int k = 0; k < 32; ++k) {
            float4 av = *(const float4*)&As[k][ty * 4];
            float4 bv = *(const float4*)&Bs[k][tx * 4];
            float a[4] = {av.x, av.y, av.z, av.w};
            float c[4] = {bv.x, bv.y, bv.z, bv.w};
            #pragma unroll
            for (int i = 0; i < 4; ++i)
                #pragma unroll
                for (int j = 0; j < 4; ++j)
                    acc[i][j] = fmaf(a[i], c[j], acc[i][j]);
        }
        __syncthreads();
    }

    float* Gb = G + (size_t)b * GRAM;
    #pragma unroll
    for (int i = 0; i < 4; ++i) {
        int m = ty * 4 + i;
        if (m >= HW) continue;
        #pragma unroll
        for (int j = 0; j < 4; ++j) {
            int n = tx * 4 + j;
            if (n < HW) Gb[m * 49 + n] = acc[i][j];
        }
    }
}

// ---------------------------------------------------------------------------
// Kernel 3: generic FC  Y[M,N] = act(X[M,K] @ W[N,K]^T + bias)
// 64x64 block tile, BK=16, 16x16 threads, 4x4 micro-tile.
// smem stride 68: keeps float4 reads 16B-aligned, limits STS conflicts to 2-way.
// M, N multiples of 64; K arbitrary (guarded).
// ---------------------------------------------------------------------------
__global__ void fc_kernel(const float* __restrict__ X, const float* __restrict__ W,
                          const float* __restrict__ bias, float* __restrict__ Y,
                          int M, int N, int K, int doRelu) {
    __shared__ __align__(16) float As[16][68];
    __shared__ __align__(16) float Bs[16][68];
    int t  = threadIdx.x;
    int tx = t & 15, ty = t >> 4;
    int bm = blockIdx.y * 64;
    int bn = blockIdx.x * 64;

    float acc[4][4] = {};

    for (int k0 = 0; k0 < K; k0 += 16) {
        #pragma unroll
        for (int q = t; q < 16 * 64; q += 256) {
            int m = q >> 4, k = q & 15;
            int gk = k0 + k;
            float a = 0.0f, bb = 0.0f;
            if (gk < K) {
                a  = X[(size_t)(bm + m) * K + gk];
                bb = W[(size_t)(bn + m) * K + gk];
            }
            As[k][m] = a;
            Bs[k][m] = bb;
        }
        __syncthreads();
        #pragma unroll
        for (int k = 0; k < 16; ++k) {
            float4 av = *(const float4*)&As[k][ty * 4];
            float4 bv = *(const float4*)&Bs[k][tx * 4];
            float a[4] = {av.x, av.y, av.z, av.w};
            float c[4] = {bv.x, bv.y, bv.z, bv.w};
            #pragma unroll
            for (int i = 0; i < 4; ++i)
                #pragma unroll
                for (int j = 0; j < 4; ++j)
                    acc[i][j] = fmaf(a[i], c[j], acc[i][j]);
        }
        __syncthreads();
    }

    #pragma unroll
    for (int i = 0; i < 4; ++i) {
        int m = bm + ty * 4 + i;
        #pragma unroll
        for (int j = 0; j < 4; ++j) {
            int n = bn + tx * 4 + j;
            float v = acc[i][j] + bias[n];
            if (doRelu) v = fmaxf(v, 0.0f);
            Y[(size_t)m * N + n] = v;
        }
    }
}

// ---------------------------------------------------------------------------
// Kernel 4: FC3  out[b, n] = y2[b] . W3[n] + b3[n],  N=4.  Warp per output.
// ---------------------------------------------------------------------------
__global__ void fc3_kernel(const float* __restrict__ X, const float* __restrict__ W3,
                           const float* __restrict__ b3, float* __restrict__ out) {
    int b    = blockIdx.x;
    int w    = threadIdx.x >> 5;   // 0..3
    int lane = threadIdx.x & 31;
    const float* xr = X  + (size_t)b * REP;
    const float* wr = W3 + (size_t)w * REP;
    float s = 0.0f;
    #pragma unroll 8
    for (int k = lane; k < REP; k += 32)
        s = fmaf(xr[k], wr[k], s);
    #pragma unroll
    for (int o = 16; o; o >>= 1)
        s += __shfl_xor_sync(0xffffffffu, s, o);
    if (lane == 0) out[b * 4 + w] = s + b3[w];
}

// ---------------------------------------------------------------------------
extern "C" void kernel_launch(void* const* d_in, const int* in_sizes, int n_in,
                              void* d_out, int out_size) {
    const float* patch1 = (const float*)d_in[0];
    const float* patch2 = (const float*)d_in[1];
    const float* W1     = (const float*)d_in[2];
    const float* b1     = (const float*)d_in[3];
    const float* W2     = (const float*)d_in[4];
    const float* b2     = (const float*)d_in[5];
    const float* W3     = (const float*)d_in[6];
    const float* b3     = (const float*)d_in[7];
    float* out = (float*)d_out;

    float *G, *W1g, *Y1, *Y2;
    cudaGetSymbolAddress((void**)&G,   g_G);
    cudaGetSymbolAddress((void**)&W1g, g_W1g);
    cudaGetSymbolAddress((void**)&Y1,  g_Y1);
    cudaGetSymbolAddress((void**)&Y2,  g_Y2);

    // 1. Fold FC1 weight through the correlation scatter
    {
        int total = REP * GRAM;
        build_w1g_kernel<<<(total + 255) / 256, 256>>>(W1, W1g);
    }
    // 2. Batched Gram: G[b] = x1[b]^T x2[b]
    gram_kernel<<<NB, 256>>>(patch1, patch2, G);
    // 3. FC1': Y1 = relu(G @ W1g^T + b1)   (M=1024, N=1024, K=2401)
    {
        dim3 grid(REP / 64, NB / 64);
        fc_kernel<<<grid, 256>>>(G, W1g, b1, Y1, NB, REP, GRAM, 1);
    }
    // 4. FC2: Y2 = relu(Y1 @ W2^T + b2)    (K=1024)
    {
        dim3 grid(REP / 64, NB / 64);
        fc_kernel<<<grid, 256>>>(Y1, W2, b2, Y2, NB, REP, REP, 1);
    }
    // 5. FC3: out = Y2 @ W3^T + b3
    fc3_kernel<<<NB, 128>>>(Y2, W3, b3, out);
}

// round 2
// speedup vs baseline: 2.2609x; 2.2609x over previous
#include <cuda_runtime.h>

// Problem constants
#define NB   1024        // batch (RoIs)
#define NC   256         // channels
#define HW   49          // 7*7 spatial
#define FEAT 12544       // 256*49
#define REP  1024
#define KC   640         // compact Gram K (625 live + 15 pad)

// Scratch (device globals; no allocations allowed)
__device__ float g_Gc [NB  * KC];   // 2.6 MB compact Gram
__device__ float g_W1c[REP * KC];   // 2.6 MB folded+compacted FC1 weight
__device__ float g_Y1 [NB  * REP];  // 4 MB
__device__ float g_Y2 [NB  * REP];  // 4 MB

// Parity-pair tables: compact axis index a (0..24) -> (i, i2), i≡i2 (mod 2).
// a = PFX[i] + (i2>>1)
__device__ __constant__ int c_I1[25] = {0,0,0,0, 1,1,1, 2,2,2,2, 3,3,3, 4,4,4,4, 5,5,5, 6,6,6,6};
__device__ __constant__ int c_I2[25] = {0,2,4,6, 1,3,5, 0,2,4,6, 1,3,5, 0,2,4,6, 1,3,5, 0,2,4,6};
__device__ __constant__ int c_PFX[7] = {0,4,7,11,14,18,21};

// ---------------------------------------------------------------------------
// Kernel 1: fold + compact W1[1024, 12544] -> W1c[1024, 640].
// compact k = a*25 + c; (i,i2)=pair[a], (j,j2)=pair[c];
// ph=(i2-i+14)/2, pw=(j2-j+14)/2, f=(ph*16+pw)*49 + i*7+j.
// ---------------------------------------------------------------------------
__global__ void build_w1c_kernel(const float* __restrict__ W1, float* __restrict__ W1c) {
    int idx = blockIdx.x * blockDim.x + threadIdx.x;
    if (idx >= REP * KC) return;
    int r = idx / KC;
    int k = idx - r * KC;
    float v = 0.0f;
    if (k < 625) {
        int a = k / 25, c = k - a * 25;
        int i = c_I1[a], i2 = c_I2[a];
        int j = c_I1[c], j2 = c_I2[c];
        int ph = (i2 - i + 14) >> 1;
        int pw = (j2 - j + 14) >> 1;
        int f  = (ph * 16 + pw) * 49 + i * 7 + j;
        v = W1[(size_t)r * FEAT + f];
    }
    W1c[idx] = v;
}

// ---------------------------------------------------------------------------
// Kernel 2: batched compact Gram.  For each b:
//   Gc[b][a*25+c] = sum_ch x1[b,ch,i,j] * x2[b,ch,i2,j2]
// computed as a full 49x49 Gram in registers (64x64 tile, 4x4 micro),
// epilogue scatters only the 625 even-displacement entries + zero pad.
// ---------------------------------------------------------------------------
__global__ void gram_kernel(const float* __restrict__ x1,
                            const float* __restrict__ x2,
                            float* __restrict__ Gc) {
    __shared__ __align__(16) float As[32][64];
    __shared__ __align__(16) float Bs[32][64];
    int b = blockIdx.x;
    int t = threadIdx.x;
    int tx = t & 15, ty = t >> 4;
    const float* X1 = x1 + (size_t)b * NC * HW;
    const float* X2 = x2 + (size_t)b * NC * HW;

    float acc[4][4] = {};

    for (int k0 = 0; k0 < NC; k0 += 32) {
        #pragma unroll
        for (int q = t; q < 32 * 64; q += 256) {
            int k = q >> 6, m = q & 63;
            float a = 0.0f, bb = 0.0f;
            if (m < HW) {
                a  = X1[(k0 + k) * HW + m];
                bb = X2[(k0 + k) * HW + m];
            }
            As[k][m] = a;
            Bs[k][m] = bb;
        }
        __syncthreads();
        #pragma unroll
        for (int k = 0; k < 32; ++k) {
            float4 av = *(const float4*)&As[k][ty * 4];
            float4 bv = *(const float4*)&Bs[k][tx * 4];
            float a[4] = {av.x, av.y, av.z, av.w};
            float c[4] = {bv.x, bv.y, bv.z, bv.w};
            #pragma unroll
            for (int i = 0; i < 4; ++i)
                #pragma unroll
                for (int j = 0; j < 4; ++j)
                    acc[i][j] = fmaf(a[i], c[j], acc[i][j]);
        }
        __syncthreads();
    }

    float* Gb = Gc + (size_t)b * KC;
    if (t < 15) Gb[625 + t] = 0.0f;   // zero pad K 625..639
    #pragma unroll
    for (int ii = 0; ii < 4; ++ii) {
        int m = ty * 4 + ii;          // ij
        if (m >= HW) continue;
        int i = m / 7, j = m - i * 7;
        #pragma unroll
        for (int jj = 0; jj < 4; ++jj) {
            int n = tx * 4 + jj;      // ij2
            if (n >= HW) continue;
            int i2 = n / 7, j2 = n - i2 * 7;
            if ((((i ^ i2) | (j ^ j2)) & 1) == 0) {
                int a = c_PFX[i] + (i2 >> 1);
                int c = c_PFX[j] + (j2 >> 1);
                Gb[a * 25 + c] = acc[ii][jj];
            }
        }
    }
}

// ---------------------------------------------------------------------------
// Kernel 3: FC  Y[M,N] = act(X[M,K] @ W[N,K]^T + bias)
// BM=128, BN=64, BK=16, 256 threads, 8x4 micro-tile, double-buffered smem.
// Requires: M%128==0, N%64==0, K%16==0, rows 16B-aligned (K%4==0).
// ---------------------------------------------------------------------------
__global__ __launch_bounds__(256) void fc_kernel(
        const float* __restrict__ X, const float* __restrict__ W,
        const float* __restrict__ bias, float* __restrict__ Y,
        int M, int N, int K, int doRelu) {
    __shared__ __align__(16) float As[2][16][132];
    __shared__ __align__(16) float Bs[2][16][68];
    int t  = threadIdx.x;
    int tx = t & 15, ty = t >> 4;
    int bm = blockIdx.y * 128;
    int bn = blockIdx.x * 64;
    const float* Xg = X + (size_t)bm * K;
    const float* Wg = W + (size_t)bn * K;

    int m0  = t >> 2;          // 0..63
    int kq4 = (t & 3) * 4;     // 0,4,8,12

    float acc[8][4] = {};
    float4 ra0, ra1, rb0;

    // prologue: tile 0
    ra0 = *(const float4*)&Xg[(size_t)m0 * K + kq4];
    ra1 = *(const float4*)&Xg[(size_t)(m0 + 64) * K + kq4];
    rb0 = *(const float4*)&Wg[(size_t)m0 * K + kq4];
    As[0][kq4 + 0][m0] = ra0.x; As[0][kq4 + 1][m0] = ra0.y;
    As[0][kq4 + 2][m0] = ra0.z; As[0][kq4 + 3][m0] = ra0.w;
    As[0][kq4 + 0][m0 + 64] = ra1.x; As[0][kq4 + 1][m0 + 64] = ra1.y;
    As[0][kq4 + 2][m0 + 64] = ra1.z; As[0][kq4 + 3][m0 + 64] = ra1.w;
    Bs[0][kq4 + 0][m0] = rb0.x; Bs[0][kq4 + 1][m0] = rb0.y;
    Bs[0][kq4 + 2][m0] = rb0.z; Bs[0][kq4 + 3][m0] = rb0.w;
    __syncthreads();

    int KT = K >> 4;
    int buf = 0;
    for (int kt = 0; kt < KT; ++kt) {
        if (kt + 1 < KT) {
            int k0n = (kt + 1) << 4;
            ra0 = *(const float4*)&Xg[(size_t)m0 * K + k0n + kq4];
            ra1 = *(const float4*)&Xg[(size_t)(m0 + 64) * K + k0n + kq4];
            rb0 = *(const float4*)&Wg[(size_t)m0 * K + k0n + kq4];
        }
        #pragma unroll
        for (int k = 0; k < 16; ++k) {
            float4 a0 = *(const float4*)&As[buf][k][ty * 8];
            float4 a1 = *(const float4*)&As[buf][k][ty * 8 + 4];
            float4 b0 = *(const float4*)&Bs[buf][k][tx * 4];
            float a[8] = {a0.x, a0.y, a0.z, a0.w, a1.x, a1.y, a1.z, a1.w};
            float c[4] = {b0.x, b0.y, b0.z, b0.w};
            #pragma unroll
            for (int i = 0; i < 8; ++i)
                #pragma unroll
                for (int j = 0; j < 4; ++j)
                    acc[i][j] = fmaf(a[i], c[j], acc[i][j]);
        }
        if (kt + 1 < KT) {
            int nb = buf ^ 1;
            As[nb][kq4 + 0][m0] = ra0.x; As[nb][kq4 + 1][m0] = ra0.y;
            As[nb][kq4 + 2][m0] = ra0.z; As[nb][kq4 + 3][m0] = ra0.w;
            As[nb][kq4 + 0][m0 + 64] = ra1.x; As[nb][kq4 + 1][m0 + 64] = ra1.y;
            As[nb][kq4 + 2][m0 + 64] = ra1.z; As[nb][kq4 + 3][m0 + 64] = ra1.w;
            Bs[nb][kq4 + 0][m0] = rb0.x; Bs[nb][kq4 + 1][m0] = rb0.y;
            Bs[nb][kq4 + 2][m0] = rb0.z; Bs[nb][kq4 + 3][m0] = rb0.w;
            buf = nb;
        }
        __syncthreads();
    }

    float4 bv = *(const float4*)&bias[bn + tx * 4];
    float bsv[4] = {bv.x, bv.y, bv.z, bv.w};
    #pragma unroll
    for (int i = 0; i < 8; ++i) {
        int row = bm + ty * 8 + i;
        float4 o;
        o.x = acc[i][0] + bsv[0];
        o.y = acc[i][1] + bsv[1];
        o.z = acc[i][2] + bsv[2];
        o.w = acc[i][3] + bsv[3];
        if (doRelu) {
            o.x = fmaxf(o.x, 0.0f); o.y = fmaxf(o.y, 0.0f);
            o.z = fmaxf(o.z, 0.0f); o.w = fmaxf(o.w, 0.0f);
        }
        *(float4*)&Y[(size_t)row * N + bn + tx * 4] = o;
    }
}

// ---------------------------------------------------------------------------
// Kernel 4: FC3  out[b, n] = y2[b] . W3[n] + b3[n],  N=4.  Warp per output.
// ---------------------------------------------------------------------------
__global__ void fc3_kernel(const float* __restrict__ X, const float* __restrict__ W3,
                           const float* __restrict__ b3, float* __restrict__ out) {
    int b    = blockIdx.x;
    int w    = threadIdx.x >> 5;   // 0..3
    int lane = threadIdx.x & 31;
    const float* xr = X  + (size_t)b * REP;
    const float* wr = W3 + (size_t)w * REP;
    float s = 0.0f;
    #pragma unroll 8
    for (int k = lane; k < REP; k += 32)
        s = fmaf(xr[k], wr[k], s);
    #pragma unroll
    for (int o = 16; o; o >>= 1)
        s += __shfl_xor_sync(0xffffffffu, s, o);
    if (lane == 0) out[b * 4 + w] = s + b3[w];
}

// ---------------------------------------------------------------------------
extern "C" void kernel_launch(void* const* d_in, const int* in_sizes, int n_in,
                              void* d_out, int out_size) {
    const float* patch1 = (const float*)d_in[0];
    const float* patch2 = (const float*)d_in[1];
    const float* W1     = (const float*)d_in[2];
    const float* b1     = (const float*)d_in[3];
    const float* W2     = (const float*)d_in[4];
    const float* b2     = (const float*)d_in[5];
    const float* W3     = (const float*)d_in[6];
    const float* b3     = (const float*)d_in[7];
    float* out = (float*)d_out;

    float *Gc, *W1c, *Y1, *Y2;
    cudaGetSymbolAddress((void**)&Gc,  g_Gc);
    cudaGetSymbolAddress((void**)&W1c, g_W1c);
    cudaGetSymbolAddress((void**)&Y1,  g_Y1);
    cudaGetSymbolAddress((void**)&Y2,  g_Y2);

    // 1. Fold + compact FC1 weight
    {
        int total = REP * KC;
        build_w1c_kernel<<<(total + 255) / 256, 256>>>(W1, W1c);
    }
    // 2. Batched compact Gram
    gram_kernel<<<NB, 256>>>(patch1, patch2, Gc);
    // 3. FC1': Y1 = relu(Gc @ W1c^T + b1)   (M=1024, N=1024, K=640)
    {
        dim3 grid(REP / 64, NB / 128);
        fc_kernel<<<grid, 256>>>(Gc, W1c, b1, Y1, NB, REP, KC, 1);
    }
    // 4. FC2: Y2 = relu(Y1 @ W2^T + b2)    (K=1024)
    {
        dim3 grid(REP / 64, NB / 128);
        fc_kernel<<<grid, 256>>>(Y1, W2, b2, Y2, NB, REP, REP, 1);
    }
    // 5. FC3: out = Y2 @ W3^T + b3
    fc3_kernel<<<NB, 128>>>(Y2, W3, b3, out);
}